// round 1
// baseline (speedup 1.0000x reference)
#include <cuda_runtime.h>
#include <math.h>
#include <stdint.h>

// Problem constants
#define Bsz  16
#define Cch  256
#define Och  256
#define Hh   64
#define Ww   64
#define HW   4096      // Hh*Ww
#define Tdim 512
#define Eexp 4

// -------- device scratch (static, allocation-free) --------
__device__ float g_pooled[Bsz * Cch];                    // [b][c]
__device__ float g_rw[Bsz * Eexp];                       // [b][e]
__device__ float g_beff[Bsz * Och];                      // [b][o]
__device__ float g_weff[(size_t)Bsz * 9 * Cch * Och];    // [b][kk][c][o]  (o innermost -> coalesced GEMM A loads)

// ============================================================
// K1: pooled = mean over HxW.  One block per (b,c).
// ============================================================
__global__ __launch_bounds__(256) void pool_kernel(const float* __restrict__ x) {
    int bc = blockIdx.x;                       // b*Cch + c
    const float4* xp = (const float4*)(x + (size_t)bc * HW);
    int t = threadIdx.x;
    float s = 0.f;
#pragma unroll
    for (int i = 0; i < 4; i++) {
        float4 v = xp[t + i * 256];
        s += v.x + v.y + v.z + v.w;
    }
#pragma unroll
    for (int o = 16; o; o >>= 1) s += __shfl_down_sync(0xffffffffu, s, o);
    __shared__ float ws[8];
    if ((t & 31) == 0) ws[t >> 5] = s;
    __syncthreads();
    if (t < 8) {
        s = ws[t];
#pragma unroll
        for (int o = 4; o; o >>= 1) s += __shfl_down_sync(0xffu, s, o);
        if (t == 0) g_pooled[bc] = s * (1.0f / HW);
    }
}

// ============================================================
// K2: router.  One block per batch sample, 256 threads.
// Produces g_rw[b][e] and g_beff[b][o].
// ============================================================
__global__ __launch_bounds__(256) void router_kernel(
    const float* __restrict__ te,
    const float* __restrict__ Wq, const float* __restrict__ bq,
    const float* __restrict__ Wk, const float* __restrict__ bk,
    const float* __restrict__ Wv, const float* __restrict__ bv,
    const float* __restrict__ Wm1, const float* __restrict__ bm1,
    const float* __restrict__ Wm2, const float* __restrict__ bm2,
    const float* __restrict__ Wc, const float* __restrict__ bcv,
    const float* __restrict__ expert_b)
{
    int b = blockIdx.x;
    int t = threadIdx.x;
    __shared__ float s_te[Tdim];
    __shared__ float s_pool[Cch];
    __shared__ float s_xatt[Cch];
    __shared__ float s_h1[64];
    __shared__ float s_xmix[Cch];
    __shared__ float s_rw[Eexp];

    s_pool[t] = g_pooled[b * Cch + t];
    s_te[t]       = te[b * Tdim + t];
    s_te[t + 256] = te[b * Tdim + t + 256];
    __syncthreads();

    // q = time_emb @ Wq.T + bq ; k = pooled @ Wk.T + bk ; v = pooled @ Wv.T + bv
    float q = bq[t];
    const float* wq = Wq + (size_t)t * Tdim;
    for (int i = 0; i < Tdim; i++) q = fmaf(wq[i], s_te[i], q);
    float kv = bk[t];
    const float* wk = Wk + (size_t)t * Cch;
    for (int i = 0; i < Cch; i++) kv = fmaf(wk[i], s_pool[i], kv);
    float v = bv[t];
    const float* wv = Wv + (size_t)t * Cch;
    for (int i = 0; i < Cch; i++) v = fmaf(wv[i], s_pool[i], v);

    float attn = 1.0f / (1.0f + expf(-(q * kv)));
    float xa = v * attn;
    s_xatt[t] = xa;
    __syncthreads();

    if (t < 64) {
        float a = bm1[t];
        const float* w = Wm1 + (size_t)t * Cch;
        for (int i = 0; i < Cch; i++) a = fmaf(w[i], s_xatt[i], a);
        // exact GELU: 0.5*x*(1+erf(x/sqrt(2)))
        s_h1[t] = 0.5f * a * (1.0f + erff(a * 0.7071067811865476f));
    }
    __syncthreads();

    float h = bm2[t];
    const float* w2 = Wm2 + (size_t)t * 64;
    for (int i = 0; i < 64; i++) h = fmaf(w2[i], s_h1[i], h);
    s_xmix[t] = xa + h;
    __syncthreads();

    if (t < Eexp) {
        float l = bcv[t];
        const float* wc = Wc + (size_t)t * Cch;
        for (int i = 0; i < Cch; i++) l = fmaf(wc[i], s_xmix[i], l);
        float r = tanhf(l);
        s_rw[t] = r;
        g_rw[b * Eexp + t] = r;
    }
    __syncthreads();

    float be = 0.f;
#pragma unroll
    for (int e = 0; e < Eexp; e++) be = fmaf(s_rw[e], expert_b[e * Och + t], be);
    g_beff[b * Och + t] = be;
}

// ============================================================
// K3: mix expert weights -> g_weff[b][kk][c][o].
// One thread per (c,o) pair; reads 9 contiguous floats per expert,
// writes coalesced along o for every (b,kk).
// ============================================================
__global__ __launch_bounds__(256) void mix_kernel(const float* __restrict__ ew) {
    __shared__ float s_rw[Bsz * Eexp];
    if (threadIdx.x < Bsz * Eexp) s_rw[threadIdx.x] = g_rw[threadIdx.x];
    __syncthreads();

    int gid = blockIdx.x * 256 + threadIdx.x;   // 0 .. 65535
    int o = gid & 255;
    int c = gid >> 8;

    float we[Eexp][9];
#pragma unroll
    for (int e = 0; e < Eexp; e++) {
        const float* p = ew + ((size_t)((e * Och + o) * Cch + c)) * 9;
#pragma unroll
        for (int k = 0; k < 9; k++) we[e][k] = p[k];
    }
#pragma unroll 1
    for (int b = 0; b < Bsz; b++) {
        float r0 = s_rw[b * 4 + 0], r1 = s_rw[b * 4 + 1];
        float r2 = s_rw[b * 4 + 2], r3 = s_rw[b * 4 + 3];
#pragma unroll
        for (int k = 0; k < 9; k++) {
            float w = r0 * we[0][k] + r1 * we[1][k] + r2 * we[2][k] + r3 * we[3][k];
            g_weff[(((size_t)(b * 9 + k) * Cch + c) << 8) + o] = w;
        }
    }
}

// ============================================================
// K4: implicit-GEMM conv.  Per CTA: one (b, 128-o tile, 128-hw tile).
// K loop: 9 taps (outer) x 256 channels (BK=8 steps).
// ============================================================
#define BM 128
#define BN 128
#define BK 8

__global__ __launch_bounds__(256) void conv_kernel(const float* __restrict__ x,
                                                   float* __restrict__ out)
{
    int nt = blockIdx.x;   // 0..31 (HW tiles, 2 image rows each)
    int mt = blockIdx.y;   // 0..1  (O tiles)
    int b  = blockIdx.z;   // 0..15

    __shared__ float sA[BK][BM];
    __shared__ float sB[BK][BN];

    int tid = threadIdx.x;
    int tx = tid & 15;      // N micro-tile
    int ty = tid >> 4;      // M micro-tile
    int lc = tid >> 5;      // 0..7 channel row for loads
    int l32 = (tid & 31);   // lane group
    int ls = l32 * 4;       // spatial base for B loads

    int h0 = nt * 2;        // first image row of this N tile
    const float* xb = x + (size_t)b * Cch * HW;

    float acc[8][8];
#pragma unroll
    for (int i = 0; i < 8; i++)
#pragma unroll
        for (int j = 0; j < 8; j++) acc[i][j] = 0.f;

#pragma unroll 1
    for (int kk = 0; kk < 9; kk++) {
        int dh = (kk / 3) - 1;
        int dw = (kk % 3) - 1;
        const float* wbase = g_weff + (size_t)(b * 9 + kk) * Cch * Och;   // [c][o]

#pragma unroll 1
        for (int c0 = 0; c0 < Cch; c0 += BK) {
            // ---- load A tile: w_eff[c0+lc][mt*128 + l32*4 .. +3], float4 coalesced
            {
                int c = c0 + lc;
                float4 wv = *(const float4*)(wbase + (size_t)c * Och + mt * BM + ls);
                *(float4*)&sA[lc][ls] = wv;
            }
            // ---- load B tile: shifted x with edge masking
            {
                int c = c0 + lc;
                const float* xr = xb + (size_t)c * HW;
#pragma unroll
                for (int i = 0; i < 4; i++) {
                    int s  = ls + i;
                    int hh = h0 + (s >> 6) + dh;
                    int ww = (s & 63) + dw;
                    float v = 0.f;
                    if (hh >= 0 && hh < Hh && ww >= 0 && ww < Ww)
                        v = xr[hh * Ww + ww];
                    sB[lc][s] = v;
                }
            }
            __syncthreads();

#pragma unroll
            for (int c = 0; c < BK; c++) {
                float a[8], bb[8];
#pragma unroll
                for (int i = 0; i < 8; i += 4) *(float4*)&a[i]  = *(float4*)&sA[c][ty * 8 + i];
#pragma unroll
                for (int j = 0; j < 8; j += 4) *(float4*)&bb[j] = *(float4*)&sB[c][tx * 8 + j];
#pragma unroll
                for (int i = 0; i < 8; i++)
#pragma unroll
                    for (int j = 0; j < 8; j++)
                        acc[i][j] = fmaf(a[i], bb[j], acc[i][j]);
            }
            __syncthreads();
        }
    }

    // ---- epilogue: add per-(b,o) bias, write [B,O,H,W]
#pragma unroll
    for (int i = 0; i < 8; i++) {
        int o = mt * BM + ty * 8 + i;
        float bias = g_beff[b * Och + o];
        float* orow = out + ((size_t)(b * Och + o)) * HW + nt * BN + tx * 8;
        float4 v0 = make_float4(acc[i][0] + bias, acc[i][1] + bias,
                                acc[i][2] + bias, acc[i][3] + bias);
        float4 v1 = make_float4(acc[i][4] + bias, acc[i][5] + bias,
                                acc[i][6] + bias, acc[i][7] + bias);
        *(float4*)(orow)     = v0;
        *(float4*)(orow + 4) = v1;
    }
}

// ============================================================
// launch
// ============================================================
extern "C" void kernel_launch(void* const* d_in, const int* in_sizes, int n_in,
                              void* d_out, int out_size)
{
    const float* x        = (const float*)d_in[0];
    const float* time_emb = (const float*)d_in[1];
    const float* Wq  = (const float*)d_in[2];
    const float* bq  = (const float*)d_in[3];
    const float* Wk  = (const float*)d_in[4];
    const float* bk  = (const float*)d_in[5];
    const float* Wv  = (const float*)d_in[6];
    const float* bv  = (const float*)d_in[7];
    const float* Wm1 = (const float*)d_in[8];
    const float* bm1 = (const float*)d_in[9];
    const float* Wm2 = (const float*)d_in[10];
    const float* bm2 = (const float*)d_in[11];
    const float* Wc  = (const float*)d_in[12];
    const float* bc  = (const float*)d_in[13];
    const float* expert_w = (const float*)d_in[14];
    const float* expert_b = (const float*)d_in[15];
    float* out = (float*)d_out;

    pool_kernel<<<Bsz * Cch, 256>>>(x);
    router_kernel<<<Bsz, 256>>>(time_emb, Wq, bq, Wk, bk, Wv, bv,
                                Wm1, bm1, Wm2, bm2, Wc, bc, expert_b);
    mix_kernel<<<(Och * Cch) / 256, 256>>>(expert_w);

    dim3 grid(HW / BN, Och / BM, Bsz);
    conv_kernel<<<grid, 256>>>(x, out);
}

// round 5
// speedup vs baseline: 3.2675x; 3.2675x over previous
#include <cuda_runtime.h>
#include <math.h>
#include <stdint.h>

// Problem constants
#define Bsz  16
#define Cch  256
#define Och  256
#define Hh   64
#define Ww   64
#define HW   4096
#define Tdim 512
#define Eexp 4

// ---------------- device scratch (static, allocation-free) ----------------
__device__ float g_pooled[Bsz * Cch];                    // [b][c]
__device__ float g_rw[Bsz * Eexp];                       // [b][e]
__device__ float g_beff[Bsz * Och];                      // [b][o]
__device__ float g_weff[(size_t)Bsz * 9 * Och * Cch];    // [b][kk][o][c] (tf32-rounded)
__device__ float g_xt[(size_t)Bsz * HW * Cch];           // [b][s][c]     (NHWC, tf32-rounded)

// ---------------- PTX helpers (sm_80-baseline only; no tcgen05) ----------------
__device__ __forceinline__ uint32_t smem_u32(const void* p) {
    uint32_t a;
    asm("{ .reg .u64 t; cvta.to.shared.u64 t, %1; cvt.u32.u64 %0, t; }" : "=r"(a) : "l"(p));
    return a;
}
__device__ __forceinline__ float to_tf32(float x) {
    uint32_t u;
    asm("cvt.rna.tf32.f32 %0, %1;" : "=r"(u) : "f"(x));
    return __uint_as_float(u);
}
__device__ __forceinline__ void cp16(uint32_t dst, const void* src, uint32_t nbytes) {
    asm volatile("cp.async.cg.shared.global [%0], [%1], 16, %2;"
                 :: "r"(dst), "l"(src), "r"(nbytes));
}
#define CP_COMMIT() asm volatile("cp.async.commit_group;" ::: "memory")
#define CP_WAIT1()  asm volatile("cp.async.wait_group 1;" ::: "memory")

__device__ __forceinline__ void mma_tf32(float* d, const uint32_t* a, const uint32_t* b) {
    asm volatile(
        "mma.sync.aligned.m16n8k8.row.col.f32.tf32.tf32.f32 "
        "{%0,%1,%2,%3}, {%4,%5,%6,%7}, {%8,%9}, {%0,%1,%2,%3};"
        : "+f"(d[0]), "+f"(d[1]), "+f"(d[2]), "+f"(d[3])
        : "r"(a[0]), "r"(a[1]), "r"(a[2]), "r"(a[3]), "r"(b[0]), "r"(b[1]));
}

// ============================================================
// K0: transpose x -> x_t NHWC [b][s][c], tf32-rounded
// ============================================================
__global__ __launch_bounds__(256) void transpose_kernel(const float* __restrict__ x) {
    __shared__ float tile[32][33];
    int st = blockIdx.x;   // spatial tile (HW/32 = 128)
    int ct = blockIdx.y;   // channel tile (256/32 = 8)
    int b  = blockIdx.z;
    int tx = threadIdx.x & 31, ty = threadIdx.x >> 5;
    const float* xp = x + ((size_t)(b * Cch + ct * 32)) * HW + st * 32;
#pragma unroll
    for (int i = 0; i < 32; i += 8)
        tile[ty + i][tx] = xp[(size_t)(ty + i) * HW + tx];
    __syncthreads();
    float* op = g_xt + ((size_t)b * HW + st * 32) * Cch + ct * 32;
#pragma unroll
    for (int i = 0; i < 32; i += 8)
        op[(size_t)(ty + i) * Cch + tx] = to_tf32(tile[tx][ty + i]);
}

// ============================================================
// K1: pooled = mean over HxW.  One block per (b,c).
// ============================================================
__global__ __launch_bounds__(256) void pool_kernel(const float* __restrict__ x) {
    int bc = blockIdx.x;
    const float4* xp = (const float4*)(x + (size_t)bc * HW);
    int t = threadIdx.x;
    float s = 0.f;
#pragma unroll
    for (int i = 0; i < 4; i++) {
        float4 v = xp[t + i * 256];
        s += v.x + v.y + v.z + v.w;
    }
#pragma unroll
    for (int o = 16; o; o >>= 1) s += __shfl_down_sync(0xffffffffu, s, o);
    __shared__ float ws[8];
    if ((t & 31) == 0) ws[t >> 5] = s;
    __syncthreads();
    if (t < 8) {
        s = ws[t];
#pragma unroll
        for (int o = 4; o; o >>= 1) s += __shfl_down_sync(0xffu, s, o);
        if (t == 0) g_pooled[bc] = s * (1.0f / HW);
    }
}

// ============================================================
// K2: router.  One block per batch sample.
// ============================================================
__global__ __launch_bounds__(256) void router_kernel(
    const float* __restrict__ te,
    const float* __restrict__ Wq, const float* __restrict__ bq,
    const float* __restrict__ Wk, const float* __restrict__ bk,
    const float* __restrict__ Wv, const float* __restrict__ bv,
    const float* __restrict__ Wm1, const float* __restrict__ bm1,
    const float* __restrict__ Wm2, const float* __restrict__ bm2,
    const float* __restrict__ Wc, const float* __restrict__ bcv,
    const float* __restrict__ expert_b)
{
    int b = blockIdx.x;
    int t = threadIdx.x;
    __shared__ float s_te[Tdim];
    __shared__ float s_pool[Cch];
    __shared__ float s_xatt[Cch];
    __shared__ float s_h1[64];
    __shared__ float s_xmix[Cch];
    __shared__ float s_rw[Eexp];

    s_pool[t] = g_pooled[b * Cch + t];
    s_te[t]       = te[b * Tdim + t];
    s_te[t + 256] = te[b * Tdim + t + 256];
    __syncthreads();

    float q = bq[t];
    const float* wq = Wq + (size_t)t * Tdim;
    for (int i = 0; i < Tdim; i++) q = fmaf(wq[i], s_te[i], q);
    float kv = bk[t];
    const float* wk = Wk + (size_t)t * Cch;
    for (int i = 0; i < Cch; i++) kv = fmaf(wk[i], s_pool[i], kv);
    float v = bv[t];
    const float* wv = Wv + (size_t)t * Cch;
    for (int i = 0; i < Cch; i++) v = fmaf(wv[i], s_pool[i], v);

    float attn = 1.0f / (1.0f + expf(-(q * kv)));
    float xa = v * attn;
    s_xatt[t] = xa;
    __syncthreads();

    if (t < 64) {
        float a = bm1[t];
        const float* w = Wm1 + (size_t)t * Cch;
        for (int i = 0; i < Cch; i++) a = fmaf(w[i], s_xatt[i], a);
        s_h1[t] = 0.5f * a * (1.0f + erff(a * 0.7071067811865476f));
    }
    __syncthreads();

    float h = bm2[t];
    const float* w2 = Wm2 + (size_t)t * 64;
    for (int i = 0; i < 64; i++) h = fmaf(w2[i], s_h1[i], h);
    s_xmix[t] = xa + h;
    __syncthreads();

    if (t < Eexp) {
        float l = bcv[t];
        const float* wc = Wc + (size_t)t * Cch;
        for (int i = 0; i < Cch; i++) l = fmaf(wc[i], s_xmix[i], l);
        float r = tanhf(l);
        s_rw[t] = r;
        g_rw[b * Eexp + t] = r;
    }
    __syncthreads();

    float be = 0.f;
#pragma unroll
    for (int e = 0; e < Eexp; e++) be = fmaf(s_rw[e], expert_b[e * Och + t], be);
    g_beff[b * Och + t] = be;
}

// ============================================================
// K3: mix expert weights -> g_weff[b][kk][o][c], tf32-rounded
// ============================================================
__global__ __launch_bounds__(256) void mix_kernel(const float* __restrict__ ew) {
    __shared__ float s_rw[Bsz * Eexp];
    if (threadIdx.x < Bsz * Eexp) s_rw[threadIdx.x] = g_rw[threadIdx.x];
    __syncthreads();

    int gid = blockIdx.x * 256 + threadIdx.x;   // 0 .. 65535
    int c = gid & 255;
    int o = gid >> 8;

    float we[Eexp][9];
#pragma unroll
    for (int e = 0; e < Eexp; e++) {
        const float* p = ew + ((size_t)((e * Och + o) * Cch + c)) * 9;
#pragma unroll
        for (int k = 0; k < 9; k++) we[e][k] = p[k];
    }
#pragma unroll 1
    for (int b = 0; b < Bsz; b++) {
        float r0 = s_rw[b * 4 + 0], r1 = s_rw[b * 4 + 1];
        float r2 = s_rw[b * 4 + 2], r3 = s_rw[b * 4 + 3];
#pragma unroll
        for (int k = 0; k < 9; k++) {
            float w = r0 * we[0][k] + r1 * we[1][k] + r2 * we[2][k] + r3 * we[3][k];
            g_weff[(((size_t)(b * 9 + k) * Och + o) << 8) + c] = to_tf32(w);
        }
    }
}

// ============================================================
// K4: mma.sync TF32 implicit-GEMM conv (cp.async 3-stage pipeline).
// CTA tile: 128 spatial (M) x 128 O (N), K = 9*256 in 72 chunks of 32.
// 8 warps, warp tile 64x32 (m16n8k8 grid 4x4).
// ============================================================
#define BM 128
#define BN 128
#define BK 32
#define LDA 36                                  // padded row stride (floats)
#define STAGE_FLOATS ((BM + BN) * LDA)          // 9216 floats = 36864 B
#define CONV_SMEM (3 * STAGE_FLOATS * 4)        // 110592 B

__device__ __forceinline__ void load_chunk(uint32_t sA, uint32_t sB,
                                           const float* __restrict__ xtb,
                                           const float* __restrict__ wbB,
                                           int chunk, int tid, int h0)
{
    int kk = chunk >> 3;
    int c0 = (chunk & 7) * 32;
    int dh = kk / 3 - 1, dw = kk % 3 - 1;
    const float* wb = wbB + (size_t)kk * (Och * Cch);
    // A tile: 128 spatial rows x 32 ch (tap-shifted, zero-filled at edges)
#pragma unroll
    for (int i = 0; i < 4; i++) {
        int idx = i * 256 + tid;                // 0..1023
        int r = idx >> 3, cq = idx & 7;
        int hh = h0 + (r >> 6) + dh;
        int ww = (r & 63) + dw;
        bool ok = ((unsigned)hh < 64u) && ((unsigned)ww < 64u);
        const float* g = ok ? (xtb + (size_t)(hh * 64 + ww) * Cch + c0 + cq * 4) : xtb;
        cp16(sA + (uint32_t)(r * LDA + cq * 4) * 4, g, ok ? 16u : 0u);
    }
    // B tile: 128 o rows x 32 ch
#pragma unroll
    for (int i = 0; i < 4; i++) {
        int idx = i * 256 + tid;
        int r = idx >> 3, cq = idx & 7;
        const float* g = wb + (size_t)r * Cch + c0 + cq * 4;
        cp16(sB + (uint32_t)(r * LDA + cq * 4) * 4, g, 16u);
    }
    CP_COMMIT();
}

__global__ __launch_bounds__(256) void conv_mma_kernel(float* __restrict__ out) {
    extern __shared__ float smf[];
    uint32_t sbase = smem_u32(smf);
    int tid = threadIdx.x;
    int wid = tid >> 5, lane = tid & 31;
    int warp_m = wid & 1;       // 2 x 64 along M
    int warp_n = wid >> 1;      // 4 x 32 along N

    int nt = blockIdx.x;        // spatial tile 0..31 (2 image rows)
    int bn = blockIdx.y;        // N tile 0..1
    int b  = blockIdx.z;
    int h0 = nt * 2;

    const float* xtb = g_xt + (size_t)b * HW * Cch;
    const float* wbB = g_weff + ((size_t)(b * 9) * Och + bn * BN) * Cch;

    uint32_t stA[3], stB[3];
#pragma unroll
    for (int s = 0; s < 3; s++) {
        stA[s] = sbase + (uint32_t)(s * STAGE_FLOATS) * 4;
        stB[s] = stA[s] + (uint32_t)(BM * LDA) * 4;
    }

    float acc[4][4][4];
#pragma unroll
    for (int i = 0; i < 4; i++)
#pragma unroll
        for (int j = 0; j < 4; j++)
#pragma unroll
            for (int k = 0; k < 4; k++) acc[i][j][k] = 0.f;

    load_chunk(stA[0], stB[0], xtb, wbB, 0, tid, h0);
    load_chunk(stA[1], stB[1], xtb, wbB, 1, tid, h0);
    CP_WAIT1();
    __syncthreads();

    int fr = lane >> 2;         // fragment row/col group
    int fc = lane & 3;

#pragma unroll 1
    for (int i = 0; i < 72; i++) {
        if (i + 2 < 72) {
            int s2 = (i + 2) % 3;
            load_chunk(stA[s2], stB[s2], xtb, wbB, i + 2, tid, h0);
        } else {
            CP_COMMIT();        // keep wait_group accounting uniform
        }
        const float* As = smf + (size_t)(i % 3) * STAGE_FLOATS;
        const float* Bs = As + BM * LDA;

#pragma unroll
        for (int k8 = 0; k8 < 4; k8++) {
            int k0 = k8 * 8;
            uint32_t af[4][4], bf[4][2];
#pragma unroll
            for (int mt = 0; mt < 4; mt++) {
                int m0 = warp_m * 64 + mt * 16;
                af[mt][0] = __float_as_uint(As[(m0 + fr) * LDA + k0 + fc]);
                af[mt][1] = __float_as_uint(As[(m0 + fr + 8) * LDA + k0 + fc]);
                af[mt][2] = __float_as_uint(As[(m0 + fr) * LDA + k0 + fc + 4]);
                af[mt][3] = __float_as_uint(As[(m0 + fr + 8) * LDA + k0 + fc + 4]);
            }
#pragma unroll
            for (int nt2 = 0; nt2 < 4; nt2++) {
                int n0 = warp_n * 32 + nt2 * 8;
                bf[nt2][0] = __float_as_uint(Bs[(n0 + fr) * LDA + k0 + fc]);
                bf[nt2][1] = __float_as_uint(Bs[(n0 + fr) * LDA + k0 + fc + 4]);
            }
#pragma unroll
            for (int mt = 0; mt < 4; mt++)
#pragma unroll
                for (int nt2 = 0; nt2 < 4; nt2++)
                    mma_tf32(acc[mt][nt2], af[mt], bf[nt2]);
        }
        CP_WAIT1();
        __syncthreads();
    }

    // ---- epilogue: stage acc through smem, coalesced float4 stores ----
    float* ep = smf;            // [n 128][m 128], row stride 132
#pragma unroll
    for (int mt = 0; mt < 4; mt++) {
#pragma unroll
        for (int nt2 = 0; nt2 < 4; nt2++) {
            int rr = warp_m * 64 + mt * 16 + fr;
            int cc = warp_n * 32 + nt2 * 8 + 2 * fc;
            ep[cc * 132 + rr]           = acc[mt][nt2][0];
            ep[(cc + 1) * 132 + rr]     = acc[mt][nt2][1];
            ep[cc * 132 + rr + 8]       = acc[mt][nt2][2];
            ep[(cc + 1) * 132 + rr + 8] = acc[mt][nt2][3];
        }
    }
    __syncthreads();

    const float* bias = g_beff + b * Och + bn * BN;
    size_t obase = ((size_t)(b * Och + bn * BN)) * HW + nt * BM;
#pragma unroll
    for (int i = 0; i < 16; i++) {
        int idx = i * 256 + tid;    // 0..4095
        int o = idx >> 5, q = idx & 31;
        float bz = bias[o];
        const float* s = ep + o * 132 + q * 4;
        float4 v = make_float4(s[0] + bz, s[1] + bz, s[2] + bz, s[3] + bz);
        *(float4*)(out + obase + (size_t)o * HW + q * 4) = v;
    }
}

// ============================================================
// launch
// ============================================================
extern "C" void kernel_launch(void* const* d_in, const int* in_sizes, int n_in,
                              void* d_out, int out_size)
{
    const float* x        = (const float*)d_in[0];
    const float* time_emb = (const float*)d_in[1];
    const float* Wq  = (const float*)d_in[2];
    const float* bq  = (const float*)d_in[3];
    const float* Wk  = (const float*)d_in[4];
    const float* bk  = (const float*)d_in[5];
    const float* Wv  = (const float*)d_in[6];
    const float* bv  = (const float*)d_in[7];
    const float* Wm1 = (const float*)d_in[8];
    const float* bm1 = (const float*)d_in[9];
    const float* Wm2 = (const float*)d_in[10];
    const float* bm2 = (const float*)d_in[11];
    const float* Wc  = (const float*)d_in[12];
    const float* bc  = (const float*)d_in[13];
    const float* expert_w = (const float*)d_in[14];
    const float* expert_b = (const float*)d_in[15];
    float* out = (float*)d_out;

    cudaFuncSetAttribute(conv_mma_kernel, cudaFuncAttributeMaxDynamicSharedMemorySize, CONV_SMEM);

    dim3 tgrid(HW / 32, Cch / 32, Bsz);
    transpose_kernel<<<tgrid, 256>>>(x);
    pool_kernel<<<Bsz * Cch, 256>>>(x);
    router_kernel<<<Bsz, 256>>>(time_emb, Wq, bq, Wk, bk, Wv, bv,
                                Wm1, bm1, Wm2, bm2, Wc, bc, expert_b);
    mix_kernel<<<(Och * Cch) / 256, 256>>>(expert_w);

    dim3 grid(HW / BM, Och / BN, Bsz);
    conv_mma_kernel<<<grid, 256, CONV_SMEM>>>(out);
}